// round 3
// baseline (speedup 1.0000x reference)
#include <cuda_runtime.h>
#include <math.h>

#define H      1024
#define H4     256          // H/4
#define VOUT   32000
#define ML     128
#define ATT    129          // ML + 1
#define GRID   148
#define BLOCK  512
#define WPB    (BLOCK/32)   // 16 warps per block
#define NWARPS (GRID*WPB)   // 2368

// ---------------- device scratch (static, no allocation) ----------------
__device__ float g_h[2][H];
__device__ float g_enc_out[ATT * H];
__device__ float g_attn[ATT];
__device__ float g_ctx[H];
__device__ float g_comb[H];
__device__ float g_logits[VOUT];
__device__ unsigned long long g_pmax[GRID];  // per-CTA packed (max,argmax)
__device__ float g_psum[GRID];               // per-CTA sumexp wrt its own max
__device__ int g_tok;

__device__ unsigned g_bar_count = 0;
__device__ unsigned g_bar_gen   = 0;

// ---------------- helpers ----------------
__device__ __forceinline__ float wredsum(float v) {
#pragma unroll
    for (int o = 16; o > 0; o >>= 1) v += __shfl_xor_sync(0xffffffffu, v, o);
    return v;
}
__device__ __forceinline__ float wredmax(float v) {
#pragma unroll
    for (int o = 16; o > 0; o >>= 1) v = fmaxf(v, __shfl_xor_sync(0xffffffffu, v, o));
    return v;
}
__device__ __forceinline__ unsigned long long wredmaxu64(unsigned long long v) {
#pragma unroll
    for (int o = 16; o > 0; o >>= 1) {
        unsigned long long q = __shfl_xor_sync(0xffffffffu, v, o);
        if (q > v) v = q;
    }
    return v;
}

__device__ __forceinline__ unsigned long long packf(float v, int idx) {
    unsigned u = __float_as_uint(v);
    u = (u & 0x80000000u) ? ~u : (u | 0x80000000u);   // totally ordered float bits
    return ((unsigned long long)u << 32) | (unsigned)(~(unsigned)idx); // tie -> lowest idx
}
__device__ __forceinline__ float unpack_max(unsigned long long p) {
    unsigned u = (unsigned)(p >> 32);
    unsigned b = (u & 0x80000000u) ? (u & 0x7fffffffu) : ~u;
    return __uint_as_float(b);
}
__device__ __forceinline__ int unpack_idx(unsigned long long p) {
    return (int)(~(unsigned)(p & 0xffffffffu));
}

__device__ __forceinline__ float dot4(float4 a, float4 b) {
    return a.x * b.x + a.y * b.y + a.z * b.z + a.w * b.w;
}

// online softmax update on a packed-best + local sum (lane0 only)
__device__ __forceinline__ void online_upd(unsigned long long& best, float& s,
                                           float a, int row) {
    unsigned long long p = packf(a, row);
    if (p > best) {
        float mold = unpack_max(best);
        s = s * expf(mold - a) + 1.f;
        best = p;
    } else {
        s += expf(a - unpack_max(best));
    }
}

// ---------------- grid-wide barrier (CG grid.sync pattern) ----------------
__device__ __forceinline__ unsigned ld_acq(unsigned* p) {
    unsigned v;
    asm volatile("ld.acquire.gpu.u32 %0, [%1];" : "=r"(v) : "l"(p) : "memory");
    return v;
}
__device__ __forceinline__ void st_rel(unsigned* p, unsigned v) {
    asm volatile("st.release.gpu.u32 [%0], %1;" :: "l"(p), "r"(v) : "memory");
}

__device__ __forceinline__ void gsync() {
    __syncthreads();
    if (threadIdx.x == 0) {
        unsigned gen = ld_acq(&g_bar_gen);
        __threadfence();
        if (atomicAdd(&g_bar_count, 1) == GRID - 1) {
            g_bar_count = 0;
            st_rel(&g_bar_gen, gen + 1);
        } else {
            while (ld_acq(&g_bar_gen) == gen) { }
        }
    }
    __syncthreads();
}

// ---------------- shared-memory layout ----------------
struct Smem {
    float e[ATT];                // attention softmax weights
    float part[WPB][33];         // ctx partial sums (padded)
    float gh[8][4];              // gru/comb warp-pair exchange
    unsigned long long best[WPB];
    float wsum[WPB];
    float bf[4];                 // scalar broadcasts
    unsigned long long bu;
};

// ---------------- phases ----------------

// GRU step: warp pair (w, w+8), w<7: row = w*GRID + cta.
// x-side (w<7) computes Wih dots; h-side (8..14) computes Whh dots.
__device__ __forceinline__ void gru_phase(
    const float* __restrict__ Wih, const float* __restrict__ Whh,
    const float* __restrict__ bih, const float* __restrict__ bhh,
    const float* __restrict__ x, const float* __restrict__ h,
    float* __restrict__ ho, float* __restrict__ enc_row, Smem* sm)
{
    int wib = threadIdx.x >> 5;
    int lane = threadIdx.x & 31;
    int wp = wib & 7;
    bool xs = (wib < 7);
    bool hs = (wib >= 8 && wib < 15);
    int row = wp * GRID + (int)blockIdx.x;
    bool act = (xs || hs) && row < H;

    float a0 = 0.f, a1 = 0.f, a2 = 0.f;
    if (act) {
        const float*  W  = xs ? Wih : Whh;
        const float4* v4 = (const float4*)(xs ? x : h);
        const float4* W0 = (const float4*)(W + (size_t)row * H);
        const float4* W1 = (const float4*)(W + (size_t)(row + H) * H);
        const float4* W2 = (const float4*)(W + (size_t)(row + 2 * H) * H);
#pragma unroll 4
        for (int k = lane; k < H4; k += 32) {
            float4 vv = v4[k];
            a0 += dot4(W0[k], vv);
            a1 += dot4(W1[k], vv);
            a2 += dot4(W2[k], vv);
        }
        a0 = wredsum(a0); a1 = wredsum(a1); a2 = wredsum(a2);
        if (hs && lane == 0) {
            sm->gh[wp][0] = a0; sm->gh[wp][1] = a1; sm->gh[wp][2] = a2;
        }
    }
    __syncthreads();
    if (act && xs && lane == 0) {
        float ir = a0 + bih[row];
        float iz = a1 + bih[row + H];
        float inn = a2 + bih[row + 2 * H];
        float hr = sm->gh[wp][0] + bhh[row];
        float hz = sm->gh[wp][1] + bhh[row + H];
        float hn = sm->gh[wp][2] + bhh[row + 2 * H];
        float r = 1.f / (1.f + expf(-(ir + hr)));
        float z = 1.f / (1.f + expf(-(iz + hz)));
        float n = tanhf(inn + r * hn);
        float hnew = (1.f - z) * n + z * h[row];
        ho[row] = hnew;
        if (enc_row) enc_row[row] = hnew;
    }
}

// attention softmax + context. CTAs 0..31 each produce 32 ctx elements.
__device__ __forceinline__ void ctx_phase(Smem* sm)
{
    if ((int)blockIdx.x >= 32) return;
    int wib = threadIdx.x >> 5, lane = threadIdx.x & 31;

    if (wib == 0) {
        float v[5];
        float mx = -INFINITY;
#pragma unroll
        for (int k = 0; k < 5; k++) {
            int idx = lane + 32 * k;
            v[k] = (idx < ATT) ? g_attn[idx] : -INFINITY;
            mx = fmaxf(mx, v[k]);
        }
        mx = wredmax(mx);
        float s = 0.f;
#pragma unroll
        for (int k = 0; k < 5; k++) {
            int idx = lane + 32 * k;
            if (idx < ATT) {
                float e = expf(v[k] - mx);
                sm->e[idx] = e;
                s += e;
            }
        }
        s = wredsum(s);
        if (lane == 0) sm->bf[0] = 1.f / s;
    }
    __syncthreads();

    // each warp accumulates a slice of timesteps for its 32 lanes
    int j = (int)blockIdx.x * 32 + lane;
    float acc = 0.f;
    for (int t = wib; t < ATT; t += WPB)
        acc += sm->e[t] * g_enc_out[t * H + j];
    sm->part[wib][lane] = acc;
    __syncthreads();
    if (wib == 0) {
        float a = 0.f;
#pragma unroll
        for (int w = 0; w < WPB; w++) a += sm->part[w][lane];
        g_ctx[j] = a * sm->bf[0];
    }
}

// comb = relu(comb_W @ [emb; ctx] + b): warp pair split like gru
__device__ __forceinline__ void comb_phase(
    const float* __restrict__ comb_W, const float* __restrict__ comb_b,
    const float* __restrict__ dec_emb, Smem* sm)
{
    int wib = threadIdx.x >> 5;
    int lane = threadIdx.x & 31;
    int wp = wib & 7;
    bool es = (wib < 7);                    // emb half
    bool cs = (wib >= 8 && wib < 15);       // ctx half
    int row = wp * GRID + (int)blockIdx.x;
    bool act = (es || cs) && row < H;

    float a = 0.f;
    if (act) {
        const float4* W  = (const float4*)(comb_W + (size_t)row * 2 * H + (es ? 0 : H));
        const float4* v4 = es ? (const float4*)(dec_emb + (size_t)g_tok * H)
                              : (const float4*)g_ctx;
#pragma unroll 4
        for (int k = lane; k < H4; k += 32) a += dot4(W[k], v4[k]);
        a = wredsum(a);
        if (cs && lane == 0) sm->gh[wp][0] = a;
    }
    __syncthreads();
    if (act && es && lane == 0) {
        float v = a + sm->gh[wp][0] + comb_b[row];
        g_comb[row] = fmaxf(v, 0.f);
    }
}

// logits GEMV, 2 rows per warp-iteration, online (max,argmax,sumexp) on lane0
__device__ __forceinline__ void logits_phase(
    const float* __restrict__ out_W, const float* __restrict__ out_b,
    const float* __restrict__ h, Smem* sm)
{
    int tid = threadIdx.x, lane = tid & 31, wib = tid >> 5;
    int gw = (int)blockIdx.x * WPB + wib;

    const float4* h4 = (const float4*)h;
    float4 hv[8];
#pragma unroll
    for (int i = 0; i < 8; i++) hv[i] = h4[lane + 32 * i];

    unsigned long long best = packf(-INFINITY, 0);
    float s = 0.f;

    int r0 = gw;
#pragma unroll 1
    for (int it = 0; it < 7; it++, r0 += 2 * NWARPS) {
        int r1 = r0 + NWARPS;
        bool ok1 = (r1 < VOUT);
        const float4* W0 = (const float4*)(out_W + (size_t)r0 * H);
        const float4* W1 = (const float4*)(out_W + (size_t)(ok1 ? r1 : r0) * H);
        float a0 = 0.f, a1 = 0.f;
#pragma unroll
        for (int i = 0; i < 8; i++) {
            float4 w0 = __ldcs(&W0[lane + 32 * i]);
            float4 w1 = __ldcs(&W1[lane + 32 * i]);
            a0 += dot4(w0, hv[i]);
            a1 += dot4(w1, hv[i]);
        }
        a0 = wredsum(a0);
        a1 = wredsum(a1);
        if (lane == 0) {
            a0 += out_b[r0];
            g_logits[r0] = a0;
            online_upd(best, s, a0, r0);
            if (ok1) {
                a1 += out_b[r1];
                g_logits[r1] = a1;
                online_upd(best, s, a1, r1);
            }
        }
    }
    if (lane == 0) { sm->best[wib] = best; sm->wsum[wib] = s; }
    __syncthreads();
    if (tid == 0) {
        unsigned long long cb = sm->best[0];
#pragma unroll
        for (int i = 1; i < WPB; i++) if (sm->best[i] > cb) cb = sm->best[i];
        float M = unpack_max(cb);
        float S = 0.f;
#pragma unroll
        for (int i = 0; i < WPB; i++)
            S += sm->wsum[i] * expf(unpack_max(sm->best[i]) - M);
        g_pmax[blockIdx.x] = cb;
        g_psum[blockIdx.x] = S;
    }
}

// combine 148 partials (warp0 shuffle-reduce), write logp row,
// and fuse next-step attention-logit prep (two-warp split)
__device__ __forceinline__ void out_phase(
    float* __restrict__ out, int step,
    const float* __restrict__ attn_W, const float* __restrict__ attn_b,
    const float* __restrict__ dec_emb, const float* __restrict__ h, Smem* sm)
{
    int tid = threadIdx.x, lane = tid & 31, wib = tid >> 5;

    if (wib == 0) {
        unsigned long long pm[5];
        float ps[5];
        unsigned long long best = packf(-INFINITY, 0);
#pragma unroll
        for (int k = 0; k < 5; k++) {
            int idx = lane + 32 * k;
            if (idx < GRID) {
                pm[k] = g_pmax[idx];
                ps[k] = g_psum[idx];
                if (pm[k] > best) best = pm[k];
            } else { pm[k] = 0ull; ps[k] = 0.f; }
        }
        best = wredmaxu64(best);
        float M = unpack_max(best);
        float S = 0.f;
#pragma unroll
        for (int k = 0; k < 5; k++) {
            int idx = lane + 32 * k;
            if (idx < GRID) S += ps[k] * expf(unpack_max(pm[k]) - M);
        }
        S = wredsum(S);
        if (lane == 0) {
            sm->bu = best;
            sm->bf[0] = M + logf(S);
        }
    }
    __syncthreads();
    unsigned long long gp = sm->bu;
    float lse = sm->bf[0];
    int tok = unpack_idx(gp);

    int g = (int)blockIdx.x * BLOCK + tid;
    if (g < VOUT) out[(size_t)step * VOUT + g] = g_logits[g] - lse;

    // next-step attention logits: two-warp split per CTA row
    if ((int)blockIdx.x < ATT) {
        int r = (int)blockIdx.x;
        if (wib == 0) {        // emb half
            const float4* W  = (const float4*)(attn_W + (size_t)r * 2 * H);
            const float4* e4 = (const float4*)(dec_emb + (size_t)tok * H);
            float a = 0.f;
#pragma unroll 4
            for (int k = lane; k < H4; k += 32) a += dot4(W[k], e4[k]);
            a = wredsum(a);
            if (lane == 0) sm->bf[1] = a;
        } else if (wib == 8) { // h half
            const float4* W  = (const float4*)(attn_W + (size_t)r * 2 * H + H);
            const float4* h4 = (const float4*)h;
            float a = 0.f;
#pragma unroll 4
            for (int k = lane; k < H4; k += 32) a += dot4(W[k], h4[k]);
            a = wredsum(a);
            if (lane == 0) sm->bf[2] = a;
        }
        __syncthreads();
        if (tid == 0) g_attn[r] = sm->bf[1] + sm->bf[2] + attn_b[r];
    }
    if (blockIdx.x == 0 && tid == 0) g_tok = tok;
}

// ---------------- the single persistent kernel ----------------
__global__ void __launch_bounds__(BLOCK, 1) k_all(
    const int* __restrict__ tokens,
    const float* __restrict__ enc_emb,
    const float* __restrict__ enc_Wih, const float* __restrict__ enc_Whh,
    const float* __restrict__ enc_bih, const float* __restrict__ enc_bhh,
    const float* __restrict__ dec_emb,
    const float* __restrict__ attn_W, const float* __restrict__ attn_b,
    const float* __restrict__ comb_W, const float* __restrict__ comb_b,
    const float* __restrict__ dec_Wih, const float* __restrict__ dec_Whh,
    const float* __restrict__ dec_bih, const float* __restrict__ dec_bhh,
    const float* __restrict__ out_W, const float* __restrict__ out_b,
    float* __restrict__ out)
{
    __shared__ Smem sm;
    int tid = threadIdx.x;

    // init: h0 = 0, padding row of enc_out = 0
    {
        int g = (int)blockIdx.x * BLOCK + tid;
        if (g < H) { g_h[0][g] = 0.f; g_enc_out[ML * H + g] = 0.f; }
    }
    gsync();

    // ---- encoder ----
    for (int t = 0; t < ML; t++) {
        const float* x = enc_emb + (size_t)tokens[t] * H;
        gru_phase(enc_Wih, enc_Whh, enc_bih, enc_bhh, x,
                  g_h[t & 1], g_h[(t & 1) ^ 1], g_enc_out + (size_t)t * H, &sm);
        gsync();
    }
    // final encoder hidden in g_h[0]

    // ---- decoder prep (tok = SOS = 0): attention logits (two-warp split) ----
    if ((int)blockIdx.x < ATT) {
        int r = (int)blockIdx.x;
        int wib = tid >> 5, lane = tid & 31;
        if (wib == 0) {
            const float4* W  = (const float4*)(attn_W + (size_t)r * 2 * H);
            const float4* e4 = (const float4*)dec_emb;  // row 0 (SOS)
            float a = 0.f;
#pragma unroll 4
            for (int k = lane; k < H4; k += 32) a += dot4(W[k], e4[k]);
            a = wredsum(a);
            if (lane == 0) sm.bf[1] = a;
        } else if (wib == 8) {
            const float4* W  = (const float4*)(attn_W + (size_t)r * 2 * H + H);
            const float4* h4 = (const float4*)g_h[0];
            float a = 0.f;
#pragma unroll 4
            for (int k = lane; k < H4; k += 32) a += dot4(W[k], h4[k]);
            a = wredsum(a);
            if (lane == 0) sm.bf[2] = a;
        }
        __syncthreads();
        if (tid == 0) g_attn[r] = sm.bf[1] + sm.bf[2] + attn_b[r];
    }
    if (blockIdx.x == 0 && tid == 0) g_tok = 0;
    gsync();

    // ---- decoder ----
    for (int s = 0; s < ML; s++) {
        const float* hc = g_h[s & 1];
        float* hn = g_h[(s & 1) ^ 1];

        ctx_phase(&sm);                                        gsync();
        comb_phase(comb_W, comb_b, dec_emb, &sm);              gsync();
        gru_phase(dec_Wih, dec_Whh, dec_bih, dec_bhh,
                  g_comb, hc, hn, nullptr, &sm);               gsync();
        logits_phase(out_W, out_b, hn, &sm);                   gsync();
        out_phase(out, s, attn_W, attn_b, dec_emb, hn, &sm);   gsync();
    }
}

// ---------------- host launcher ----------------
extern "C" void kernel_launch(void* const* d_in, const int* in_sizes, int n_in,
                              void* d_out, int out_size)
{
    const int*   tokens  = (const int*)  d_in[0];
    // d_in[1] = max_length (compile-time ML=128)
    const float* enc_emb = (const float*)d_in[2];
    const float* enc_Wih = (const float*)d_in[3];
    const float* enc_Whh = (const float*)d_in[4];
    const float* enc_bih = (const float*)d_in[5];
    const float* enc_bhh = (const float*)d_in[6];
    const float* dec_emb = (const float*)d_in[7];
    const float* attn_W  = (const float*)d_in[8];
    const float* attn_b  = (const float*)d_in[9];
    const float* comb_W  = (const float*)d_in[10];
    const float* comb_b  = (const float*)d_in[11];
    const float* dec_Wih = (const float*)d_in[12];
    const float* dec_Whh = (const float*)d_in[13];
    const float* dec_bih = (const float*)d_in[14];
    const float* dec_bhh = (const float*)d_in[15];
    const float* out_W   = (const float*)d_in[16];
    const float* out_b   = (const float*)d_in[17];
    float* out = (float*)d_out;

    k_all<<<GRID, BLOCK>>>(tokens, enc_emb, enc_Wih, enc_Whh, enc_bih, enc_bhh,
                           dec_emb, attn_W, attn_b, comb_W, comb_b,
                           dec_Wih, dec_Whh, dec_bih, dec_bhh,
                           out_W, out_b, out);
}

// round 4
// speedup vs baseline: 1.2272x; 1.2272x over previous
#include <cuda_runtime.h>
#include <math.h>

#define H      1024
#define H4     256          // H/4
#define VOUT   32000
#define ML     128
#define ATT    129          // ML + 1
#define GRID   148
#define BLOCK  512
#define WPB    (BLOCK/32)   // 16 warps per block
#define NWARPS (GRID*WPB)   // 2368
#define MAXSLOT 14          // max rows per warp

// ---------------- device scratch (static, no allocation) ----------------
__device__ float g_h[2][H];
__device__ float g_enc_out[ATT * H];
__device__ float g_attn[ATT];
__device__ float g_ctx[H];
__device__ float g_comb[H];
__device__ float g_logits[VOUT];
__device__ unsigned long long g_pmax[GRID];  // per-CTA packed (max,argmax)
__device__ float g_psum[GRID];               // per-CTA sumexp wrt its own max
__device__ int g_tok;

__device__ unsigned g_bar_count = 0;
__device__ unsigned g_bar_gen   = 0;

// ---------------- helpers ----------------
__device__ __forceinline__ float wredsum(float v) {
#pragma unroll
    for (int o = 16; o > 0; o >>= 1) v += __shfl_xor_sync(0xffffffffu, v, o);
    return v;
}
__device__ __forceinline__ float wredmax(float v) {
#pragma unroll
    for (int o = 16; o > 0; o >>= 1) v = fmaxf(v, __shfl_xor_sync(0xffffffffu, v, o));
    return v;
}
__device__ __forceinline__ unsigned long long wredmaxu64(unsigned long long v) {
#pragma unroll
    for (int o = 16; o > 0; o >>= 1) {
        unsigned long long q = __shfl_xor_sync(0xffffffffu, v, o);
        if (q > v) v = q;
    }
    return v;
}

__device__ __forceinline__ unsigned long long packf(float v, int idx) {
    unsigned u = __float_as_uint(v);
    u = (u & 0x80000000u) ? ~u : (u | 0x80000000u);   // totally ordered float bits
    return ((unsigned long long)u << 32) | (unsigned)(~(unsigned)idx); // tie -> lowest idx
}
__device__ __forceinline__ float unpack_max(unsigned long long p) {
    unsigned u = (unsigned)(p >> 32);
    unsigned b = (u & 0x80000000u) ? (u & 0x7fffffffu) : ~u;
    return __uint_as_float(b);
}
__device__ __forceinline__ int unpack_idx(unsigned long long p) {
    return (int)(~(unsigned)(p & 0xffffffffu));
}

__device__ __forceinline__ float dot4(float4 a, float4 b) {
    return a.x * b.x + a.y * b.y + a.z * b.z + a.w * b.w;
}

// ---------------- grid-wide barrier (CG grid.sync pattern) ----------------
__device__ __forceinline__ unsigned ld_acq(unsigned* p) {
    unsigned v;
    asm volatile("ld.acquire.gpu.u32 %0, [%1];" : "=r"(v) : "l"(p) : "memory");
    return v;
}
__device__ __forceinline__ void st_rel(unsigned* p, unsigned v) {
    asm volatile("st.release.gpu.u32 [%0], %1;" :: "l"(p), "r"(v) : "memory");
}

__device__ __forceinline__ void gsync() {
    __syncthreads();
    if (threadIdx.x == 0) {
        unsigned gen = ld_acq(&g_bar_gen);
        __threadfence();
        if (atomicAdd(&g_bar_count, 1) == GRID - 1) {
            g_bar_count = 0;
            st_rel(&g_bar_gen, gen + 1);
        } else {
            while (ld_acq(&g_bar_gen) == gen) { }
        }
    }
    __syncthreads();
}

// ---------------- shared-memory layout ----------------
struct Smem {
    float e[ATT];                 // attention softmax weights
    float part[WPB][33];          // ctx partial sums (padded)
    float slot[WPB * MAXSLOT];    // raw logits per warp slot
    float red[BLOCK];             // tree-reduction scratch
    unsigned long long best[WPB];
    float bf[4];                  // scalar broadcasts
    unsigned long long bu;
};

// ---------------- phases ----------------

// GRU step (R2 structure): warp w<7 handles row = w*GRID + cta, all 6 dots.
__device__ __forceinline__ void gru_phase(
    const float* __restrict__ Wih, const float* __restrict__ Whh,
    const float* __restrict__ bih, const float* __restrict__ bhh,
    const float* __restrict__ x, const float* __restrict__ h,
    float* __restrict__ ho, float* __restrict__ enc_row)
{
    int wib = threadIdx.x >> 5;
    int lane = threadIdx.x & 31;
    if (wib >= 7) return;
    int row = wib * GRID + (int)blockIdx.x;
    if (row >= H) return;

    const float4* x4 = (const float4*)x;
    const float4* h4 = (const float4*)h;
    const float4* Wir = (const float4*)(Wih + (size_t)row * H);
    const float4* Wiz = (const float4*)(Wih + (size_t)(row + H) * H);
    const float4* Win = (const float4*)(Wih + (size_t)(row + 2 * H) * H);
    const float4* Whr = (const float4*)(Whh + (size_t)row * H);
    const float4* Whz = (const float4*)(Whh + (size_t)(row + H) * H);
    const float4* Whn = (const float4*)(Whh + (size_t)(row + 2 * H) * H);

    float ir = 0.f, iz = 0.f, inn = 0.f, hr = 0.f, hz = 0.f, hn = 0.f;
#pragma unroll 4
    for (int k = lane; k < H4; k += 32) {
        float4 xv = x4[k], hv = h4[k];
        ir  += dot4(Wir[k], xv);
        iz  += dot4(Wiz[k], xv);
        inn += dot4(Win[k], xv);
        hr  += dot4(Whr[k], hv);
        hz  += dot4(Whz[k], hv);
        hn  += dot4(Whn[k], hv);
    }
    ir = wredsum(ir);  iz = wredsum(iz);  inn = wredsum(inn);
    hr = wredsum(hr);  hz = wredsum(hz);  hn  = wredsum(hn);

    if (lane == 0) {
        ir  += bih[row];          hr += bhh[row];
        iz  += bih[row + H];      hz += bhh[row + H];
        inn += bih[row + 2 * H];  hn += bhh[row + 2 * H];
        float r = 1.f / (1.f + expf(-(ir + hr)));
        float z = 1.f / (1.f + expf(-(iz + hz)));
        float n = tanhf(inn + r * hn);
        float hnew = (1.f - z) * n + z * h[row];
        ho[row] = hnew;
        if (enc_row) enc_row[row] = hnew;
    }
}

// attention softmax + context. CTAs 0..31 each produce 32 ctx elements.
__device__ __forceinline__ void ctx_phase(Smem* sm)
{
    if ((int)blockIdx.x >= 32) return;
    int wib = threadIdx.x >> 5, lane = threadIdx.x & 31;

    if (wib == 0) {
        float v[5];
        float mx = -INFINITY;
#pragma unroll
        for (int k = 0; k < 5; k++) {
            int idx = lane + 32 * k;
            v[k] = (idx < ATT) ? g_attn[idx] : -INFINITY;
            mx = fmaxf(mx, v[k]);
        }
        mx = wredmax(mx);
        float s = 0.f;
#pragma unroll
        for (int k = 0; k < 5; k++) {
            int idx = lane + 32 * k;
            if (idx < ATT) {
                float e = expf(v[k] - mx);
                sm->e[idx] = e;
                s += e;
            }
        }
        s = wredsum(s);
        if (lane == 0) sm->bf[0] = 1.f / s;
    }
    __syncthreads();

    // each warp accumulates a slice of timesteps for its 32 lanes
    int j = (int)blockIdx.x * 32 + lane;
    float acc = 0.f;
    for (int t = wib; t < ATT; t += WPB)
        acc += sm->e[t] * g_enc_out[t * H + j];
    sm->part[wib][lane] = acc;
    __syncthreads();
    if (wib == 0) {
        float a = 0.f;
#pragma unroll
        for (int w = 0; w < WPB; w++) a += sm->part[w][lane];
        g_ctx[j] = a * sm->bf[0];
    }
}

// comb = relu(comb_W @ [emb; ctx] + b)  (R2 structure: one warp per row)
__device__ __forceinline__ void comb_phase(
    const float* __restrict__ comb_W, const float* __restrict__ comb_b,
    const float* __restrict__ dec_emb)
{
    int wib = threadIdx.x >> 5;
    int lane = threadIdx.x & 31;
    if (wib >= 7) return;
    int row = wib * GRID + (int)blockIdx.x;
    if (row >= H) return;
    int tok = g_tok;
    const float4* W  = (const float4*)(comb_W + (size_t)row * 2 * H);
    const float4* e4 = (const float4*)(dec_emb + (size_t)tok * H);
    const float4* c4 = (const float4*)g_ctx;
    float a = 0.f;
#pragma unroll 4
    for (int k = lane; k < H4; k += 32) a += dot4(W[k], e4[k]);
#pragma unroll 4
    for (int k = lane; k < H4; k += 32) a += dot4(W[k + H4], c4[k]);
    a = wredsum(a);
    if (lane == 0) {
        a += comb_b[row];
        g_comb[row] = fmaxf(a, 0.f);
    }
}

// logits GEMV: 2 rows per warp-iteration (interleaved load streams),
// branch-free slot epilogue (R2 style), per-CTA (max,argmax,sumexp) partials.
__device__ __forceinline__ void logits_phase(
    const float* __restrict__ out_W, const float* __restrict__ out_b,
    const float* __restrict__ h, Smem* sm)
{
    int tid = threadIdx.x, lane = tid & 31, wib = tid >> 5;
    int gw = (int)blockIdx.x * WPB + wib;

    if (tid < WPB * MAXSLOT) sm->slot[tid] = -INFINITY;
    __syncthreads();

    const float4* h4 = (const float4*)h;
    float4 hv[8];
#pragma unroll
    for (int i = 0; i < 8; i++) hv[i] = h4[lane + 32 * i];

    unsigned long long best = packf(-INFINITY, 0);

#pragma unroll 1
    for (int it = 0; it < 7; it++) {
        int r0 = gw + it * 2 * NWARPS;
        int r1 = r0 + NWARPS;
        bool ok1 = (r1 < VOUT);
        const float4* W0 = (const float4*)(out_W + (size_t)r0 * H);
        const float4* W1 = (const float4*)(out_W + (size_t)(ok1 ? r1 : r0) * H);
        float a0 = 0.f, a1 = 0.f;
#pragma unroll
        for (int i = 0; i < 8; i++) {
            float4 w0 = __ldcs(&W0[lane + 32 * i]);
            float4 w1 = __ldcs(&W1[lane + 32 * i]);
            a0 += dot4(w0, hv[i]);
            a1 += dot4(w1, hv[i]);
        }
        a0 = wredsum(a0);
        a1 = wredsum(a1);
        if (lane == 0) {
            a0 += out_b[r0];
            g_logits[r0] = a0;
            sm->slot[wib * MAXSLOT + 2 * it] = a0;
            unsigned long long p0 = packf(a0, r0);
            if (p0 > best) best = p0;
            if (ok1) {
                a1 += out_b[r1];
                g_logits[r1] = a1;
                sm->slot[wib * MAXSLOT + 2 * it + 1] = a1;
                unsigned long long p1 = packf(a1, r1);
                if (p1 > best) best = p1;
            }
        }
    }
    if (lane == 0) sm->best[wib] = best;
    __syncthreads();
    if (tid == 0) {
        unsigned long long b = sm->best[0];
#pragma unroll
        for (int i = 1; i < WPB; i++) if (sm->best[i] > b) b = sm->best[i];
        sm->best[0] = b;
    }
    __syncthreads();
    unsigned long long cb = sm->best[0];
    float m = unpack_max(cb);
    float e = (tid < WPB * MAXSLOT) ? expf(sm->slot[tid] - m) : 0.f;  // -inf -> 0
    sm->red[tid] = e; __syncthreads();
#pragma unroll
    for (int s = BLOCK / 2; s > 0; s >>= 1) {
        if (tid < s) sm->red[tid] += sm->red[tid + s];
        __syncthreads();
    }
    if (tid == 0) {
        g_pmax[blockIdx.x] = cb;
        g_psum[blockIdx.x] = sm->red[0];
    }
}

// combine 148 partials (warp0 shuffle-reduce), write logp row,
// and fuse next-step attention-logit prep (two-warp split)
__device__ __forceinline__ void out_phase(
    float* __restrict__ out, int step,
    const float* __restrict__ attn_W, const float* __restrict__ attn_b,
    const float* __restrict__ dec_emb, const float* __restrict__ h, Smem* sm)
{
    int tid = threadIdx.x, lane = tid & 31, wib = tid >> 5;

    if (wib == 0) {
        unsigned long long pm[5];
        float ps[5];
        unsigned long long best = packf(-INFINITY, 0);
#pragma unroll
        for (int k = 0; k < 5; k++) {
            int idx = lane + 32 * k;
            if (idx < GRID) {
                pm[k] = g_pmax[idx];
                ps[k] = g_psum[idx];
                if (pm[k] > best) best = pm[k];
            } else { pm[k] = 0ull; ps[k] = 0.f; }
        }
        best = wredmaxu64(best);
        float M = unpack_max(best);
        float S = 0.f;
#pragma unroll
        for (int k = 0; k < 5; k++) {
            int idx = lane + 32 * k;
            if (idx < GRID) S += ps[k] * expf(unpack_max(pm[k]) - M);
        }
        S = wredsum(S);
        if (lane == 0) {
            sm->bu = best;
            sm->bf[0] = M + logf(S);
        }
    }
    __syncthreads();
    unsigned long long gp = sm->bu;
    float lse = sm->bf[0];
    int tok = unpack_idx(gp);

    int g = (int)blockIdx.x * BLOCK + tid;
    if (g < VOUT) out[(size_t)step * VOUT + g] = g_logits[g] - lse;

    // next-step attention logits: two-warp split per CTA row
    if ((int)blockIdx.x < ATT) {
        int r = (int)blockIdx.x;
        if (wib == 0) {        // emb half
            const float4* W  = (const float4*)(attn_W + (size_t)r * 2 * H);
            const float4* e4 = (const float4*)(dec_emb + (size_t)tok * H);
            float a = 0.f;
#pragma unroll 4
            for (int k = lane; k < H4; k += 32) a += dot4(W[k], e4[k]);
            a = wredsum(a);
            if (lane == 0) sm->bf[1] = a;
        } else if (wib == 8) { // h half
            const float4* W  = (const float4*)(attn_W + (size_t)r * 2 * H + H);
            const float4* h4 = (const float4*)h;
            float a = 0.f;
#pragma unroll 4
            for (int k = lane; k < H4; k += 32) a += dot4(W[k], h4[k]);
            a = wredsum(a);
            if (lane == 0) sm->bf[2] = a;
        }
        __syncthreads();
        if (tid == 0) g_attn[r] = sm->bf[1] + sm->bf[2] + attn_b[r];
    }
    if (blockIdx.x == 0 && tid == 0) g_tok = tok;
}

// ---------------- the single persistent kernel ----------------
__global__ void __launch_bounds__(BLOCK, 1) k_all(
    const int* __restrict__ tokens,
    const float* __restrict__ enc_emb,
    const float* __restrict__ enc_Wih, const float* __restrict__ enc_Whh,
    const float* __restrict__ enc_bih, const float* __restrict__ enc_bhh,
    const float* __restrict__ dec_emb,
    const float* __restrict__ attn_W, const float* __restrict__ attn_b,
    const float* __restrict__ comb_W, const float* __restrict__ comb_b,
    const float* __restrict__ dec_Wih, const float* __restrict__ dec_Whh,
    const float* __restrict__ dec_bih, const float* __restrict__ dec_bhh,
    const float* __restrict__ out_W, const float* __restrict__ out_b,
    float* __restrict__ out)
{
    __shared__ Smem sm;
    int tid = threadIdx.x;

    // init: h0 = 0, padding row of enc_out = 0
    {
        int g = (int)blockIdx.x * BLOCK + tid;
        if (g < H) { g_h[0][g] = 0.f; g_enc_out[ML * H + g] = 0.f; }
    }
    gsync();

    // ---- encoder ----
    for (int t = 0; t < ML; t++) {
        const float* x = enc_emb + (size_t)tokens[t] * H;
        gru_phase(enc_Wih, enc_Whh, enc_bih, enc_bhh, x,
                  g_h[t & 1], g_h[(t & 1) ^ 1], g_enc_out + (size_t)t * H);
        gsync();
    }
    // final encoder hidden in g_h[0]

    // ---- decoder prep (tok = SOS = 0): attention logits (two-warp split) ----
    if ((int)blockIdx.x < ATT) {
        int r = (int)blockIdx.x;
        int wib = tid >> 5, lane = tid & 31;
        if (wib == 0) {
            const float4* W  = (const float4*)(attn_W + (size_t)r * 2 * H);
            const float4* e4 = (const float4*)dec_emb;  // row 0 (SOS)
            float a = 0.f;
#pragma unroll 4
            for (int k = lane; k < H4; k += 32) a += dot4(W[k], e4[k]);
            a = wredsum(a);
            if (lane == 0) sm.bf[1] = a;
        } else if (wib == 8) {
            const float4* W  = (const float4*)(attn_W + (size_t)r * 2 * H + H);
            const float4* h4 = (const float4*)g_h[0];
            float a = 0.f;
#pragma unroll 4
            for (int k = lane; k < H4; k += 32) a += dot4(W[k], h4[k]);
            a = wredsum(a);
            if (lane == 0) sm.bf[2] = a;
        }
        __syncthreads();
        if (tid == 0) g_attn[r] = sm.bf[1] + sm.bf[2] + attn_b[r];
    }
    if (blockIdx.x == 0 && tid == 0) g_tok = 0;
    gsync();

    // ---- decoder ----
    for (int s = 0; s < ML; s++) {
        const float* hc = g_h[s & 1];
        float* hn = g_h[(s & 1) ^ 1];

        ctx_phase(&sm);                                        gsync();
        comb_phase(comb_W, comb_b, dec_emb);                   gsync();
        gru_phase(dec_Wih, dec_Whh, dec_bih, dec_bhh,
                  g_comb, hc, hn, nullptr);                    gsync();
        logits_phase(out_W, out_b, hn, &sm);                   gsync();
        out_phase(out, s, attn_W, attn_b, dec_emb, hn, &sm);   gsync();
    }
}

// ---------------- host launcher ----------------
extern "C" void kernel_launch(void* const* d_in, const int* in_sizes, int n_in,
                              void* d_out, int out_size)
{
    const int*   tokens  = (const int*)  d_in[0];
    // d_in[1] = max_length (compile-time ML=128)
    const float* enc_emb = (const float*)d_in[2];
    const float* enc_Wih = (const float*)d_in[3];
    const float* enc_Whh = (const float*)d_in[4];
    const float* enc_bih = (const float*)d_in[5];
    const float* enc_bhh = (const float*)d_in[6];
    const float* dec_emb = (const float*)d_in[7];
    const float* attn_W  = (const float*)d_in[8];
    const float* attn_b  = (const float*)d_in[9];
    const float* comb_W  = (const float*)d_in[10];
    const float* comb_b  = (const float*)d_in[11];
    const float* dec_Wih = (const float*)d_in[12];
    const float* dec_Whh = (const float*)d_in[13];
    const float* dec_bih = (const float*)d_in[14];
    const float* dec_bhh = (const float*)d_in[15];
    const float* out_W   = (const float*)d_in[16];
    const float* out_b   = (const float*)d_in[17];
    float* out = (float*)d_out;

    k_all<<<GRID, BLOCK>>>(tokens, enc_emb, enc_Wih, enc_Whh, enc_bih, enc_bhh,
                           dec_emb, attn_W, attn_b, comb_W, comb_b,
                           dec_Wih, dec_Whh, dec_bih, dec_bhh,
                           out_W, out_b, out);
}

// round 5
// speedup vs baseline: 1.2954x; 1.0556x over previous
#include <cuda_runtime.h>
#include <cuda_bf16.h>
#include <math.h>

#define H      1024
#define H4     256          // H/4
#define VOUT   32000
#define ML     128
#define ATT    129          // ML + 1
#define GRID   148
#define BLOCK  512
#define WPB    (BLOCK/32)   // 16 warps per block
#define NWARPS (GRID*WPB)   // 2368
#define MAXSLOT 14          // max rows per warp

// ---------------- device scratch (static, no allocation) ----------------
__device__ float g_h[2][H];
__device__ float g_enc_out[ATT * H];
__device__ float g_attn[ATT];
__device__ float g_ctx[H];
__device__ float g_comb[H];
__device__ float g_logits[VOUT];
__device__ unsigned long long g_ptop[GRID][4]; // per-CTA top-4 packed (bf16-based)
__device__ float g_psum[GRID];                 // per-CTA sumexp wrt its own max
__device__ int g_tok;
__device__ __nv_bfloat16 g_wbf[(size_t)VOUT * H];  // 64MB bf16 copy of out_W

__device__ unsigned g_bar_count = 0;
__device__ unsigned g_bar_gen   = 0;

// ---------------- helpers ----------------
__device__ __forceinline__ float wredsum(float v) {
#pragma unroll
    for (int o = 16; o > 0; o >>= 1) v += __shfl_xor_sync(0xffffffffu, v, o);
    return v;
}
__device__ __forceinline__ float wredmax(float v) {
#pragma unroll
    for (int o = 16; o > 0; o >>= 1) v = fmaxf(v, __shfl_xor_sync(0xffffffffu, v, o));
    return v;
}
__device__ __forceinline__ unsigned long long wredmaxu64(unsigned long long v) {
#pragma unroll
    for (int o = 16; o > 0; o >>= 1) {
        unsigned long long q = __shfl_xor_sync(0xffffffffu, v, o);
        if (q > v) v = q;
    }
    return v;
}

__device__ __forceinline__ unsigned long long packf(float v, int idx) {
    unsigned u = __float_as_uint(v);
    u = (u & 0x80000000u) ? ~u : (u | 0x80000000u);   // totally ordered float bits
    return ((unsigned long long)u << 32) | (unsigned)(~(unsigned)idx); // tie -> lowest idx
}
__device__ __forceinline__ float unpack_max(unsigned long long p) {
    unsigned u = (unsigned)(p >> 32);
    unsigned b = (u & 0x80000000u) ? (u & 0x7fffffffu) : ~u;
    return __uint_as_float(b);
}
__device__ __forceinline__ int unpack_idx(unsigned long long p) {
    return (int)(~(unsigned)(p & 0xffffffffu));
}

__device__ __forceinline__ float dot4(float4 a, float4 b) {
    return a.x * b.x + a.y * b.y + a.z * b.z + a.w * b.w;
}

// 8-elem bf16 dot against two float4 halves
__device__ __forceinline__ float bfdot8(uint4 w, float4 a, float4 b) {
    float2 p0 = __bfloat1622float2(*(__nv_bfloat162*)&w.x);
    float2 p1 = __bfloat1622float2(*(__nv_bfloat162*)&w.y);
    float2 p2 = __bfloat1622float2(*(__nv_bfloat162*)&w.z);
    float2 p3 = __bfloat1622float2(*(__nv_bfloat162*)&w.w);
    return p0.x*a.x + p0.y*a.y + p1.x*a.z + p1.y*a.w
         + p2.x*b.x + p2.y*b.y + p3.x*b.z + p3.y*b.w;
}

// insert p into descending top-4 (c0>=c1>=c2>=c3)
__device__ __forceinline__ void top4_ins(unsigned long long& c0, unsigned long long& c1,
                                         unsigned long long& c2, unsigned long long& c3,
                                         unsigned long long p) {
    if (p > c0)      { c3 = c2; c2 = c1; c1 = c0; c0 = p; }
    else if (p > c1) { c3 = c2; c2 = c1; c1 = p; }
    else if (p > c2) { c3 = c2; c2 = p; }
    else if (p > c3) { c3 = p; }
}

// ---------------- grid-wide barrier (CG grid.sync pattern) ----------------
__device__ __forceinline__ unsigned ld_acq(unsigned* p) {
    unsigned v;
    asm volatile("ld.acquire.gpu.u32 %0, [%1];" : "=r"(v) : "l"(p) : "memory");
    return v;
}
__device__ __forceinline__ void st_rel(unsigned* p, unsigned v) {
    asm volatile("st.release.gpu.u32 [%0], %1;" :: "l"(p), "r"(v) : "memory");
}

__device__ __forceinline__ void gsync() {
    __syncthreads();
    if (threadIdx.x == 0) {
        unsigned gen = ld_acq(&g_bar_gen);
        __threadfence();
        if (atomicAdd(&g_bar_count, 1) == GRID - 1) {
            g_bar_count = 0;
            st_rel(&g_bar_gen, gen + 1);
        } else {
            while (ld_acq(&g_bar_gen) == gen) { }
        }
    }
    __syncthreads();
}

// ---------------- shared-memory layout ----------------
struct Smem {
    float e[ATT];                 // attention softmax weights
    float part[WPB][33];          // ctx partial sums (padded)
    float slot[WPB * MAXSLOT];    // raw logits per warp slot
    float red[BLOCK];             // tree-reduction scratch
    unsigned long long wtop[WPB][4];
    unsigned long long top4[4];
    unsigned long long cand[4];
    float bf[4];                  // scalar broadcasts
    unsigned long long bu;
};

// ---------------- phases ----------------

// GRU step: warp w<7 handles row = w*GRID + cta, all 6 dots.
__device__ __forceinline__ void gru_phase(
    const float* __restrict__ Wih, const float* __restrict__ Whh,
    const float* __restrict__ bih, const float* __restrict__ bhh,
    const float* __restrict__ x, const float* __restrict__ h,
    float* __restrict__ ho, float* __restrict__ enc_row)
{
    int wib = threadIdx.x >> 5;
    int lane = threadIdx.x & 31;
    if (wib >= 7) return;
    int row = wib * GRID + (int)blockIdx.x;
    if (row >= H) return;

    const float4* x4 = (const float4*)x;
    const float4* h4 = (const float4*)h;
    const float4* Wir = (const float4*)(Wih + (size_t)row * H);
    const float4* Wiz = (const float4*)(Wih + (size_t)(row + H) * H);
    const float4* Win = (const float4*)(Wih + (size_t)(row + 2 * H) * H);
    const float4* Whr = (const float4*)(Whh + (size_t)row * H);
    const float4* Whz = (const float4*)(Whh + (size_t)(row + H) * H);
    const float4* Whn = (const float4*)(Whh + (size_t)(row + 2 * H) * H);

    float ir = 0.f, iz = 0.f, inn = 0.f, hr = 0.f, hz = 0.f, hn = 0.f;
#pragma unroll 4
    for (int k = lane; k < H4; k += 32) {
        float4 xv = x4[k], hv = h4[k];
        ir  += dot4(Wir[k], xv);
        iz  += dot4(Wiz[k], xv);
        inn += dot4(Win[k], xv);
        hr  += dot4(Whr[k], hv);
        hz  += dot4(Whz[k], hv);
        hn  += dot4(Whn[k], hv);
    }
    ir = wredsum(ir);  iz = wredsum(iz);  inn = wredsum(inn);
    hr = wredsum(hr);  hz = wredsum(hz);  hn  = wredsum(hn);

    if (lane == 0) {
        ir  += bih[row];          hr += bhh[row];
        iz  += bih[row + H];      hz += bhh[row + H];
        inn += bih[row + 2 * H];  hn += bhh[row + 2 * H];
        float r = 1.f / (1.f + expf(-(ir + hr)));
        float z = 1.f / (1.f + expf(-(iz + hz)));
        float n = tanhf(inn + r * hn);
        float hnew = (1.f - z) * n + z * h[row];
        ho[row] = hnew;
        if (enc_row) enc_row[row] = hnew;
    }
}

// attention softmax + context. CTAs 0..31 each produce 32 ctx elements.
__device__ __forceinline__ void ctx_phase(Smem* sm)
{
    if ((int)blockIdx.x >= 32) return;
    int wib = threadIdx.x >> 5, lane = threadIdx.x & 31;

    if (wib == 0) {
        float v[5];
        float mx = -INFINITY;
#pragma unroll
        for (int k = 0; k < 5; k++) {
            int idx = lane + 32 * k;
            v[k] = (idx < ATT) ? g_attn[idx] : -INFINITY;
            mx = fmaxf(mx, v[k]);
        }
        mx = wredmax(mx);
        float s = 0.f;
#pragma unroll
        for (int k = 0; k < 5; k++) {
            int idx = lane + 32 * k;
            if (idx < ATT) {
                float e = expf(v[k] - mx);
                sm->e[idx] = e;
                s += e;
            }
        }
        s = wredsum(s);
        if (lane == 0) sm->bf[0] = 1.f / s;
    }
    __syncthreads();

    int j = (int)blockIdx.x * 32 + lane;
    float acc = 0.f;
    for (int t = wib; t < ATT; t += WPB)
        acc += sm->e[t] * g_enc_out[t * H + j];
    sm->part[wib][lane] = acc;
    __syncthreads();
    if (wib == 0) {
        float a = 0.f;
#pragma unroll
        for (int w = 0; w < WPB; w++) a += sm->part[w][lane];
        g_ctx[j] = a * sm->bf[0];
    }
}

// comb = relu(comb_W @ [emb; ctx] + b): one warp per row
__device__ __forceinline__ void comb_phase(
    const float* __restrict__ comb_W, const float* __restrict__ comb_b,
    const float* __restrict__ dec_emb)
{
    int wib = threadIdx.x >> 5;
    int lane = threadIdx.x & 31;
    if (wib >= 7) return;
    int row = wib * GRID + (int)blockIdx.x;
    if (row >= H) return;
    int tok = g_tok;
    const float4* W  = (const float4*)(comb_W + (size_t)row * 2 * H);
    const float4* e4 = (const float4*)(dec_emb + (size_t)tok * H);
    const float4* c4 = (const float4*)g_ctx;
    float a = 0.f;
#pragma unroll 4
    for (int k = lane; k < H4; k += 32) a += dot4(W[k], e4[k]);
#pragma unroll 4
    for (int k = lane; k < H4; k += 32) a += dot4(W[k + H4], c4[k]);
    a = wredsum(a);
    if (lane == 0) {
        a += comb_b[row];
        g_comb[row] = fmaxf(a, 0.f);
    }
}

// logits GEMV on bf16 weights: 2 rows per warp-iteration, branch-free epilogue,
// per-warp top-4 (off hot loop) -> per-CTA top-4 + sumexp partials.
__device__ __forceinline__ void logits_phase(
    const float* __restrict__ out_b, const float* __restrict__ h, Smem* sm)
{
    int tid = threadIdx.x, lane = tid & 31, wib = tid >> 5;
    int gw = (int)blockIdx.x * WPB + wib;

    if (tid < WPB * MAXSLOT) sm->slot[tid] = -INFINITY;
    __syncthreads();

    // h cached: hv[2i],hv[2i+1] cover elements (lane+32i)*8 .. +7
    const float4* h4 = (const float4*)h;
    float4 hv[8];
#pragma unroll
    for (int i = 0; i < 4; i++) {
        hv[2*i]   = h4[(lane + 32*i) * 2];
        hv[2*i+1] = h4[(lane + 32*i) * 2 + 1];
    }

#pragma unroll 1
    for (int it = 0; it < 7; it++) {
        int r0 = gw + it * 2 * NWARPS;
        int r1 = r0 + NWARPS;
        bool ok1 = (r1 < VOUT);
        const uint4* W0 = (const uint4*)(g_wbf + (size_t)r0 * H);
        const uint4* W1 = (const uint4*)(g_wbf + (size_t)(ok1 ? r1 : r0) * H);
        float a0 = 0.f, a1 = 0.f;
#pragma unroll
        for (int i = 0; i < 4; i++) {
            uint4 w0 = __ldcs(&W0[lane + 32 * i]);
            uint4 w1 = __ldcs(&W1[lane + 32 * i]);
            a0 += bfdot8(w0, hv[2*i], hv[2*i+1]);
            a1 += bfdot8(w1, hv[2*i], hv[2*i+1]);
        }
        a0 = wredsum(a0);
        a1 = wredsum(a1);
        if (lane == 0) {
            a0 += out_b[r0];
            g_logits[r0] = a0;
            sm->slot[wib * MAXSLOT + 2 * it] = a0;
            if (ok1) {
                a1 += out_b[r1];
                g_logits[r1] = a1;
                sm->slot[wib * MAXSLOT + 2 * it + 1] = a1;
            }
        }
    }

    // per-warp top-4 scan (lane0, off the hot loop)
    if (lane == 0) {
        unsigned long long c0 = 0, c1 = 0, c2 = 0, c3 = 0;
#pragma unroll
        for (int n = 0; n < MAXSLOT; n++) {
            int row = gw + n * NWARPS;
            if (row < VOUT) {
                unsigned long long p = packf(sm->slot[wib * MAXSLOT + n], row);
                top4_ins(c0, c1, c2, c3, p);
            }
        }
        sm->wtop[wib][0] = c0; sm->wtop[wib][1] = c1;
        sm->wtop[wib][2] = c2; sm->wtop[wib][3] = c3;
    }
    __syncthreads();

    // warp0: pop-merge 16 warp lists -> CTA top-4
    if (wib == 0) {
        unsigned long long a0 = 0, a1 = 0, a2 = 0, a3 = 0;
        if (lane < WPB) {
            a0 = sm->wtop[lane][0]; a1 = sm->wtop[lane][1];
            a2 = sm->wtop[lane][2]; a3 = sm->wtop[lane][3];
        }
        int pos = 0;
        unsigned long long t[4];
#pragma unroll
        for (int k = 0; k < 4; k++) {
            unsigned long long head = (pos == 0) ? a0 : (pos == 1) ? a1 :
                                      (pos == 2) ? a2 : (pos == 3) ? a3 : 0ull;
            unsigned long long m = wredmaxu64(head);
            t[k] = m;
            if (head == m && pos < 4) pos++;
        }
        if (lane == 0) {
#pragma unroll
            for (int k = 0; k < 4; k++) g_ptop[blockIdx.x][k] = t[k];
            sm->bu = t[0];
        }
    }
    __syncthreads();

    // CTA sumexp wrt CTA max
    float m = unpack_max(sm->bu);
    float e = (tid < WPB * MAXSLOT) ? expf(sm->slot[tid] - m) : 0.f;
    sm->red[tid] = e; __syncthreads();
#pragma unroll
    for (int s = BLOCK / 2; s > 0; s >>= 1) {
        if (tid < s) sm->red[tid] += sm->red[tid + s];
        __syncthreads();
    }
    if (tid == 0) g_psum[blockIdx.x] = sm->red[0];
}

// global top-4 merge + lse; fp32 recheck of top-4 for exact argmax;
// write logp row; fuse next-step attention-logit prep
__device__ __forceinline__ void out_phase(
    float* __restrict__ out, int step,
    const float* __restrict__ out_W, const float* __restrict__ out_b,
    const float* __restrict__ attn_W, const float* __restrict__ attn_b,
    const float* __restrict__ dec_emb, const float* __restrict__ h, Smem* sm)
{
    int tid = threadIdx.x, lane = tid & 31, wib = tid >> 5;

    if (wib == 0) {
        // per-lane top-4 over its CTAs
        unsigned long long c0 = 0, c1 = 0, c2 = 0, c3 = 0;
        for (int cc = lane; cc < GRID; cc += 32) {
#pragma unroll
            for (int k = 0; k < 4; k++)
                top4_ins(c0, c1, c2, c3, g_ptop[cc][k]);
        }
        // pop-merge across lanes -> global top-4
        int pos = 0;
        unsigned long long t[4];
#pragma unroll
        for (int k = 0; k < 4; k++) {
            unsigned long long head = (pos == 0) ? c0 : (pos == 1) ? c1 :
                                      (pos == 2) ? c2 : (pos == 3) ? c3 : 0ull;
            unsigned long long mm = wredmaxu64(head);
            t[k] = mm;
            if (head == mm && pos < 4) pos++;
        }
        float M = unpack_max(t[0]);
        float S = 0.f;
        for (int cc = lane; cc < GRID; cc += 32)
            S += g_psum[cc] * expf(unpack_max(g_ptop[cc][0]) - M);
        S = wredsum(S);
        if (lane == 0) {
#pragma unroll
            for (int k = 0; k < 4; k++) sm->top4[k] = t[k];
            sm->bf[0] = M + logf(S);
        }
    }
    __syncthreads();
    float lse = sm->bf[0];

    // write logp row (bf16-based logits, fp32 lse)
    int g = (int)blockIdx.x * BLOCK + tid;
    if (g < VOUT) out[(size_t)step * VOUT + g] = g_logits[g] - lse;

    // fp32 recheck of the 4 candidates (warps 0..3, one row each)
    if (wib < 4) {
        int rk = unpack_idx(sm->top4[wib]);
        const float4* W = (const float4*)(out_W + (size_t)rk * H);
        const float4* h4 = (const float4*)h;
        float a = 0.f;
#pragma unroll 4
        for (int k = lane; k < H4; k += 32) a += dot4(W[k], h4[k]);
        a = wredsum(a);
        if (lane == 0) sm->cand[wib] = packf(a + out_b[rk], rk);
    }
    __syncthreads();
    unsigned long long w = sm->cand[0];
#pragma unroll
    for (int k = 1; k < 4; k++) if (sm->cand[k] > w) w = sm->cand[k];
    int tok = unpack_idx(w);

    // next-step attention logits: two-warp split per CTA row
    if ((int)blockIdx.x < ATT) {
        int r = (int)blockIdx.x;
        if (wib == 0) {        // emb half
            const float4* W  = (const float4*)(attn_W + (size_t)r * 2 * H);
            const float4* e4 = (const float4*)(dec_emb + (size_t)tok * H);
            float a = 0.f;
#pragma unroll 4
            for (int k = lane; k < H4; k += 32) a += dot4(W[k], e4[k]);
            a = wredsum(a);
            if (lane == 0) sm->bf[1] = a;
        } else if (wib == 8) { // h half
            const float4* W  = (const float4*)(attn_W + (size_t)r * 2 * H + H);
            const float4* h4 = (const float4*)h;
            float a = 0.f;
#pragma unroll 4
            for (int k = lane; k < H4; k += 32) a += dot4(W[k], h4[k]);
            a = wredsum(a);
            if (lane == 0) sm->bf[2] = a;
        }
        __syncthreads();
        if (tid == 0) g_attn[r] = sm->bf[1] + sm->bf[2] + attn_b[r];
    }
    if (blockIdx.x == 0 && tid == 0) g_tok = tok;
}

// ---------------- the single persistent kernel ----------------
__global__ void __launch_bounds__(BLOCK, 1) k_all(
    const int* __restrict__ tokens,
    const float* __restrict__ enc_emb,
    const float* __restrict__ enc_Wih, const float* __restrict__ enc_Whh,
    const float* __restrict__ enc_bih, const float* __restrict__ enc_bhh,
    const float* __restrict__ dec_emb,
    const float* __restrict__ attn_W, const float* __restrict__ attn_b,
    const float* __restrict__ comb_W, const float* __restrict__ comb_b,
    const float* __restrict__ dec_Wih, const float* __restrict__ dec_Whh,
    const float* __restrict__ dec_bih, const float* __restrict__ dec_bhh,
    const float* __restrict__ out_W, const float* __restrict__ out_b,
    float* __restrict__ out)
{
    __shared__ Smem sm;
    int tid = threadIdx.x;

    // one-time: convert out_W to bf16 (grid-stride, vectorized)
    {
        const float4* w4 = (const float4*)out_W;
        uint2* dst = (uint2*)g_wbf;
        const int n4 = VOUT * (H / 4);
        for (int i = (int)blockIdx.x * BLOCK + tid; i < n4; i += GRID * BLOCK) {
            float4 v = __ldcs(&w4[i]);
            __nv_bfloat162 lo = __floats2bfloat162_rn(v.x, v.y);
            __nv_bfloat162 hi = __floats2bfloat162_rn(v.z, v.w);
            uint2 o;
            o.x = *(unsigned*)&lo;
            o.y = *(unsigned*)&hi;
            dst[i] = o;
        }
    }

    // init: h0 = 0, padding row of enc_out = 0
    {
        int g = (int)blockIdx.x * BLOCK + tid;
        if (g < H) { g_h[0][g] = 0.f; g_enc_out[ML * H + g] = 0.f; }
    }
    gsync();

    // ---- encoder ----
    for (int t = 0; t < ML; t++) {
        const float* x = enc_emb + (size_t)tokens[t] * H;
        gru_phase(enc_Wih, enc_Whh, enc_bih, enc_bhh, x,
                  g_h[t & 1], g_h[(t & 1) ^ 1], g_enc_out + (size_t)t * H);
        gsync();
    }
    // final encoder hidden in g_h[0]

    // ---- decoder prep (tok = SOS = 0): attention logits (two-warp split) ----
    if ((int)blockIdx.x < ATT) {
        int r = (int)blockIdx.x;
        int wib = tid >> 5, lane = tid & 31;
        if (wib == 0) {
            const float4* W  = (const float4*)(attn_W + (size_t)r * 2 * H);
            const float4* e4 = (const float4*)dec_emb;  // row 0 (SOS)
            float a = 0.f;
#pragma unroll 4
            for (int k = lane; k < H4; k += 32) a += dot4(W[k], e4[k]);
            a = wredsum(a);
            if (lane == 0) sm.bf[1] = a;
        } else if (wib == 8) {
            const float4* W  = (const float4*)(attn_W + (size_t)r * 2 * H + H);
            const float4* h4 = (const float4*)g_h[0];
            float a = 0.f;
#pragma unroll 4
            for (int k = lane; k < H4; k += 32) a += dot4(W[k], h4[k]);
            a = wredsum(a);
            if (lane == 0) sm.bf[2] = a;
        }
        __syncthreads();
        if (tid == 0) g_attn[r] = sm.bf[1] + sm.bf[2] + attn_b[r];
    }
    if (blockIdx.x == 0 && tid == 0) g_tok = 0;
    gsync();

    // ---- decoder ----
    for (int s = 0; s < ML; s++) {
        const float* hc = g_h[s & 1];
        float* hn = g_h[(s & 1) ^ 1];

        ctx_phase(&sm);                                        gsync();
        comb_phase(comb_W, comb_b, dec_emb);                   gsync();
        gru_phase(dec_Wih, dec_Whh, dec_bih, dec_bhh,
                  g_comb, hc, hn, nullptr);                    gsync();
        logits_phase(out_b, hn, &sm);                          gsync();
        out_phase(out, s, out_W, out_b, attn_W, attn_b,
                  dec_emb, hn, &sm);                           gsync();
    }
}

// ---------------- host launcher ----------------
extern "C" void kernel_launch(void* const* d_in, const int* in_sizes, int n_in,
                              void* d_out, int out_size)
{
    const int*   tokens  = (const int*)  d_in[0];
    // d_in[1] = max_length (compile-time ML=128)
    const float* enc_emb = (const float*)d_in[2];
    const float* enc_Wih = (const float*)d_in[3];
    const float* enc_Whh = (const float*)d_in[4];
    const float* enc_bih = (const float*)d_in[5];
    const float* enc_bhh = (const float*)d_in[6];
    const float* dec_emb = (const float*)d_in[7];
    const float* attn_W  = (const float*)d_in[8];
    const float* attn_b  = (const float*)d_in[9];
    const float* comb_W  = (const float*)d_in[10];
    const float* comb_b  = (const float*)d_in[11];
    const float* dec_Wih = (const float*)d_in[12];
    const float* dec_Whh = (const float*)d_in[13];
    const float* dec_bih = (const float*)d_in[14];
    const float* dec_bhh = (const float*)d_in[15];
    const float* out_W   = (const float*)d_in[16];
    const float* out_b   = (const float*)d_in[17];
    float* out = (float*)d_out;

    k_all<<<GRID, BLOCK>>>(tokens, enc_emb, enc_Wih, enc_Whh, enc_bih, enc_bhh,
                           dec_emb, attn_W, attn_b, comb_W, comb_b,
                           dec_Wih, dec_Whh, dec_bih, dec_bhh,
                           out_W, out_b, out);
}

// round 6
// speedup vs baseline: 1.3101x; 1.0113x over previous
#include <cuda_runtime.h>
#include <cuda_bf16.h>
#include <math.h>

#define H      1024
#define H4     256          // H/4
#define VOUT   32000
#define ML     128
#define ATT    129          // ML + 1
#define GRID   148
#define BLOCK  512
#define WPB    (BLOCK/32)   // 16 warps per block
#define NWARPS (GRID*WPB)   // 2368
#define MAXSLOT 14          // max rows per warp

// ---------------- device scratch (static, no allocation) ----------------
__device__ float g_h[2][H];
__device__ float g_enc_out[ATT * H];
__device__ float g_attn[ATT];
__device__ float g_ctx[H];
__device__ float g_comb[H];
__device__ float g_logits[VOUT];
__device__ unsigned long long g_ptop[GRID][4]; // per-CTA top-4 packed (bf16-based)
__device__ float g_psum[GRID];                 // per-CTA sumexp wrt its own max
__device__ int g_tok;
__device__ __nv_bfloat16 g_wbf[(size_t)VOUT * H];  // 64MB bf16 copy of out_W

__device__ unsigned g_bar_count = 0;
__device__ unsigned g_bar_gen   = 0;

// ---------------- helpers ----------------
__device__ __forceinline__ float wredsum(float v) {
#pragma unroll
    for (int o = 16; o > 0; o >>= 1) v += __shfl_xor_sync(0xffffffffu, v, o);
    return v;
}
__device__ __forceinline__ float wredmax(float v) {
#pragma unroll
    for (int o = 16; o > 0; o >>= 1) v = fmaxf(v, __shfl_xor_sync(0xffffffffu, v, o));
    return v;
}
__device__ __forceinline__ unsigned long long wredmaxu64(unsigned long long v) {
#pragma unroll
    for (int o = 16; o > 0; o >>= 1) {
        unsigned long long q = __shfl_xor_sync(0xffffffffu, v, o);
        if (q > v) v = q;
    }
    return v;
}

__device__ __forceinline__ unsigned long long packf(float v, int idx) {
    unsigned u = __float_as_uint(v);
    u = (u & 0x80000000u) ? ~u : (u | 0x80000000u);   // totally ordered float bits
    return ((unsigned long long)u << 32) | (unsigned)(~(unsigned)idx); // tie -> lowest idx
}
__device__ __forceinline__ float unpack_max(unsigned long long p) {
    unsigned u = (unsigned)(p >> 32);
    unsigned b = (u & 0x80000000u) ? (u & 0x7fffffffu) : ~u;
    return __uint_as_float(b);
}
__device__ __forceinline__ int unpack_idx(unsigned long long p) {
    return (int)(~(unsigned)(p & 0xffffffffu));
}

__device__ __forceinline__ float dot4(float4 a, float4 b) {
    return a.x * b.x + a.y * b.y + a.z * b.z + a.w * b.w;
}

// 8-elem bf16 dot against two float4 halves
__device__ __forceinline__ float bfdot8(uint4 w, float4 a, float4 b) {
    float2 p0 = __bfloat1622float2(*(__nv_bfloat162*)&w.x);
    float2 p1 = __bfloat1622float2(*(__nv_bfloat162*)&w.y);
    float2 p2 = __bfloat1622float2(*(__nv_bfloat162*)&w.z);
    float2 p3 = __bfloat1622float2(*(__nv_bfloat162*)&w.w);
    return p0.x*a.x + p0.y*a.y + p1.x*a.z + p1.y*a.w
         + p2.x*b.x + p2.y*b.y + p3.x*b.z + p3.y*b.w;
}

// insert p into descending top-4 (c0>=c1>=c2>=c3)
__device__ __forceinline__ void top4_ins(unsigned long long& c0, unsigned long long& c1,
                                         unsigned long long& c2, unsigned long long& c3,
                                         unsigned long long p) {
    if (p > c0)      { c3 = c2; c2 = c1; c1 = c0; c0 = p; }
    else if (p > c1) { c3 = c2; c2 = c1; c1 = p; }
    else if (p > c2) { c3 = c2; c2 = p; }
    else if (p > c3) { c3 = p; }
}

// ---------------- grid-wide barrier (CG grid.sync pattern) ----------------
__device__ __forceinline__ unsigned ld_acq(unsigned* p) {
    unsigned v;
    asm volatile("ld.acquire.gpu.u32 %0, [%1];" : "=r"(v) : "l"(p) : "memory");
    return v;
}
__device__ __forceinline__ void st_rel(unsigned* p, unsigned v) {
    asm volatile("st.release.gpu.u32 [%0], %1;" :: "l"(p), "r"(v) : "memory");
}

__device__ __forceinline__ void gsync() {
    __syncthreads();
    if (threadIdx.x == 0) {
        unsigned gen = ld_acq(&g_bar_gen);
        __threadfence();
        if (atomicAdd(&g_bar_count, 1) == GRID - 1) {
            g_bar_count = 0;
            st_rel(&g_bar_gen, gen + 1);
        } else {
            while (ld_acq(&g_bar_gen) == gen) { }
        }
    }
    __syncthreads();
}

// ---------------- shared-memory layout ----------------
struct Smem {
    float e[ATT];                 // attention softmax weights
    float part[WPB][33];          // ctx partial sums (padded)
    float slot[WPB * MAXSLOT];    // raw logits per warp slot
    float red[BLOCK];             // tree-reduction scratch
    unsigned long long wtop[WPB][4];
    unsigned long long top4[4];
    unsigned long long cand[4];
    float bf[4];                  // scalar broadcasts
    unsigned long long bu;
};

// ---------------- phases ----------------

// GRU step: warp w<7 handles row = w*GRID + cta, all 6 dots.
__device__ __forceinline__ void gru_phase(
    const float* __restrict__ Wih, const float* __restrict__ Whh,
    const float* __restrict__ bih, const float* __restrict__ bhh,
    const float* __restrict__ x, const float* __restrict__ h,
    float* __restrict__ ho, float* __restrict__ enc_row)
{
    int wib = threadIdx.x >> 5;
    int lane = threadIdx.x & 31;
    if (wib >= 7) return;
    int row = wib * GRID + (int)blockIdx.x;
    if (row >= H) return;

    const float4* x4 = (const float4*)x;
    const float4* h4 = (const float4*)h;
    const float4* Wir = (const float4*)(Wih + (size_t)row * H);
    const float4* Wiz = (const float4*)(Wih + (size_t)(row + H) * H);
    const float4* Win = (const float4*)(Wih + (size_t)(row + 2 * H) * H);
    const float4* Whr = (const float4*)(Whh + (size_t)row * H);
    const float4* Whz = (const float4*)(Whh + (size_t)(row + H) * H);
    const float4* Whn = (const float4*)(Whh + (size_t)(row + 2 * H) * H);

    float ir = 0.f, iz = 0.f, inn = 0.f, hr = 0.f, hz = 0.f, hn = 0.f;
#pragma unroll 4
    for (int k = lane; k < H4; k += 32) {
        float4 xv = x4[k], hv = h4[k];
        ir  += dot4(Wir[k], xv);
        iz  += dot4(Wiz[k], xv);
        inn += dot4(Win[k], xv);
        hr  += dot4(Whr[k], hv);
        hz  += dot4(Whz[k], hv);
        hn  += dot4(Whn[k], hv);
    }
    ir = wredsum(ir);  iz = wredsum(iz);  inn = wredsum(inn);
    hr = wredsum(hr);  hz = wredsum(hz);  hn  = wredsum(hn);

    if (lane == 0) {
        ir  += bih[row];          hr += bhh[row];
        iz  += bih[row + H];      hz += bhh[row + H];
        inn += bih[row + 2 * H];  hn += bhh[row + 2 * H];
        float r = 1.f / (1.f + expf(-(ir + hr)));
        float z = 1.f / (1.f + expf(-(iz + hz)));
        float n = tanhf(inn + r * hn);
        float hnew = (1.f - z) * n + z * h[row];
        ho[row] = hnew;
        if (enc_row) enc_row[row] = hnew;
    }
}

// attention softmax + context. CTAs 0..31 each produce 32 ctx elements.
__device__ __forceinline__ void ctx_phase(Smem* sm)
{
    if ((int)blockIdx.x >= 32) return;
    int wib = threadIdx.x >> 5, lane = threadIdx.x & 31;

    if (wib == 0) {
        float v[5];
        float mx = -INFINITY;
#pragma unroll
        for (int k = 0; k < 5; k++) {
            int idx = lane + 32 * k;
            v[k] = (idx < ATT) ? g_attn[idx] : -INFINITY;
            mx = fmaxf(mx, v[k]);
        }
        mx = wredmax(mx);
        float s = 0.f;
#pragma unroll
        for (int k = 0; k < 5; k++) {
            int idx = lane + 32 * k;
            if (idx < ATT) {
                float e = expf(v[k] - mx);
                sm->e[idx] = e;
                s += e;
            }
        }
        s = wredsum(s);
        if (lane == 0) sm->bf[0] = 1.f / s;
    }
    __syncthreads();

    int j = (int)blockIdx.x * 32 + lane;
    float acc = 0.f;
    for (int t = wib; t < ATT; t += WPB)
        acc += sm->e[t] * g_enc_out[t * H + j];
    sm->part[wib][lane] = acc;
    __syncthreads();
    if (wib == 0) {
        float a = 0.f;
#pragma unroll
        for (int w = 0; w < WPB; w++) a += sm->part[w][lane];
        g_ctx[j] = a * sm->bf[0];
    }
}

// comb = relu(comb_W @ [emb; ctx] + b): one warp per row
__device__ __forceinline__ void comb_phase(
    const float* __restrict__ comb_W, const float* __restrict__ comb_b,
    const float* __restrict__ dec_emb)
{
    int wib = threadIdx.x >> 5;
    int lane = threadIdx.x & 31;
    if (wib >= 7) return;
    int row = wib * GRID + (int)blockIdx.x;
    if (row >= H) return;
    int tok = g_tok;
    const float4* W  = (const float4*)(comb_W + (size_t)row * 2 * H);
    const float4* e4 = (const float4*)(dec_emb + (size_t)tok * H);
    const float4* c4 = (const float4*)g_ctx;
    float a = 0.f;
#pragma unroll 4
    for (int k = lane; k < H4; k += 32) a += dot4(W[k], e4[k]);
#pragma unroll 4
    for (int k = lane; k < H4; k += 32) a += dot4(W[k + H4], c4[k]);
    a = wredsum(a);
    if (lane == 0) {
        a += comb_b[row];
        g_comb[row] = fmaxf(a, 0.f);
    }
}

// logits GEMV on bf16 weights: 4 rows per warp-iteration (16 loads in flight),
// branch-free epilogue, per-warp top-4 -> per-CTA top-4 + sumexp partials.
__device__ __forceinline__ void logits_phase(
    const float* __restrict__ out_b, const float* __restrict__ h, Smem* sm)
{
    int tid = threadIdx.x, lane = tid & 31, wib = tid >> 5;
    int gw = (int)blockIdx.x * WPB + wib;

    if (tid < WPB * MAXSLOT) sm->slot[tid] = -INFINITY;
    __syncthreads();

    // h cached: hv[2i],hv[2i+1] cover elements (lane+32i)*8 .. +7
    const float4* h4 = (const float4*)h;
    float4 hv[8];
#pragma unroll
    for (int i = 0; i < 4; i++) {
        hv[2*i]   = h4[(lane + 32*i) * 2];
        hv[2*i+1] = h4[(lane + 32*i) * 2 + 1];
    }

    // n = 0..12 are always in-bounds (gw + 12*NWARPS <= 2367+28416 < 32000)
#pragma unroll 1
    for (int it = 0; it < 3; it++) {
        int r0 = gw + (4 * it)     * NWARPS;
        int r1 = gw + (4 * it + 1) * NWARPS;
        int r2 = gw + (4 * it + 2) * NWARPS;
        int r3 = gw + (4 * it + 3) * NWARPS;
        const uint4* W0 = (const uint4*)(g_wbf + (size_t)r0 * H);
        const uint4* W1 = (const uint4*)(g_wbf + (size_t)r1 * H);
        const uint4* W2 = (const uint4*)(g_wbf + (size_t)r2 * H);
        const uint4* W3 = (const uint4*)(g_wbf + (size_t)r3 * H);
        float a0 = 0.f, a1 = 0.f, a2 = 0.f, a3 = 0.f;
#pragma unroll
        for (int i = 0; i < 4; i++) {
            uint4 w0 = __ldcs(&W0[lane + 32 * i]);
            uint4 w1 = __ldcs(&W1[lane + 32 * i]);
            uint4 w2 = __ldcs(&W2[lane + 32 * i]);
            uint4 w3 = __ldcs(&W3[lane + 32 * i]);
            a0 += bfdot8(w0, hv[2*i], hv[2*i+1]);
            a1 += bfdot8(w1, hv[2*i], hv[2*i+1]);
            a2 += bfdot8(w2, hv[2*i], hv[2*i+1]);
            a3 += bfdot8(w3, hv[2*i], hv[2*i+1]);
        }
        a0 = wredsum(a0);
        a1 = wredsum(a1);
        a2 = wredsum(a2);
        a3 = wredsum(a3);
        if (lane == 0) {
            a0 += out_b[r0];  g_logits[r0] = a0;  sm->slot[wib * MAXSLOT + 4*it]     = a0;
            a1 += out_b[r1];  g_logits[r1] = a1;  sm->slot[wib * MAXSLOT + 4*it + 1] = a1;
            a2 += out_b[r2];  g_logits[r2] = a2;  sm->slot[wib * MAXSLOT + 4*it + 2] = a2;
            a3 += out_b[r3];  g_logits[r3] = a3;  sm->slot[wib * MAXSLOT + 4*it + 3] = a3;
        }
    }
    // tail: n = 12 (always valid) and n = 13 (conditional)
    {
        int r0 = gw + 12 * NWARPS;
        int r1 = gw + 13 * NWARPS;
        bool ok1 = (r1 < VOUT);
        const uint4* W0 = (const uint4*)(g_wbf + (size_t)r0 * H);
        const uint4* W1 = (const uint4*)(g_wbf + (size_t)(ok1 ? r1 : r0) * H);
        float a0 = 0.f, a1 = 0.f;
#pragma unroll
        for (int i = 0; i < 4; i++) {
            uint4 w0 = __ldcs(&W0[lane + 32 * i]);
            uint4 w1 = __ldcs(&W1[lane + 32 * i]);
            a0 += bfdot8(w0, hv[2*i], hv[2*i+1]);
            a1 += bfdot8(w1, hv[2*i], hv[2*i+1]);
        }
        a0 = wredsum(a0);
        a1 = wredsum(a1);
        if (lane == 0) {
            a0 += out_b[r0];  g_logits[r0] = a0;  sm->slot[wib * MAXSLOT + 12] = a0;
            if (ok1) {
                a1 += out_b[r1];  g_logits[r1] = a1;  sm->slot[wib * MAXSLOT + 13] = a1;
            }
        }
    }

    // per-warp top-4 scan (lane0, off the hot loop)
    if (lane == 0) {
        unsigned long long c0 = 0, c1 = 0, c2 = 0, c3 = 0;
#pragma unroll
        for (int n = 0; n < MAXSLOT; n++) {
            int row = gw + n * NWARPS;
            if (row < VOUT) {
                unsigned long long p = packf(sm->slot[wib * MAXSLOT + n], row);
                top4_ins(c0, c1, c2, c3, p);
            }
        }
        sm->wtop[wib][0] = c0; sm->wtop[wib][1] = c1;
        sm->wtop[wib][2] = c2; sm->wtop[wib][3] = c3;
    }
    __syncthreads();

    // warp0: pop-merge 16 warp lists -> CTA top-4
    if (wib == 0) {
        unsigned long long a0 = 0, a1 = 0, a2 = 0, a3 = 0;
        if (lane < WPB) {
            a0 = sm->wtop[lane][0]; a1 = sm->wtop[lane][1];
            a2 = sm->wtop[lane][2]; a3 = sm->wtop[lane][3];
        }
        int pos = 0;
        unsigned long long t[4];
#pragma unroll
        for (int k = 0; k < 4; k++) {
            unsigned long long head = (pos == 0) ? a0 : (pos == 1) ? a1 :
                                      (pos == 2) ? a2 : (pos == 3) ? a3 : 0ull;
            unsigned long long m = wredmaxu64(head);
            t[k] = m;
            if (head == m && pos < 4) pos++;
        }
        if (lane == 0) {
#pragma unroll
            for (int k = 0; k < 4; k++) g_ptop[blockIdx.x][k] = t[k];
            sm->bu = t[0];
        }
    }
    __syncthreads();

    // CTA sumexp wrt CTA max
    float m = unpack_max(sm->bu);
    float e = (tid < WPB * MAXSLOT) ? expf(sm->slot[tid] - m) : 0.f;
    sm->red[tid] = e; __syncthreads();
#pragma unroll
    for (int s = BLOCK / 2; s > 0; s >>= 1) {
        if (tid < s) sm->red[tid] += sm->red[tid + s];
        __syncthreads();
    }
    if (tid == 0) g_psum[blockIdx.x] = sm->red[0];
}

// global top-4 merge + lse; fp32 recheck of top-4 for exact argmax;
// write logp row; fuse next-step attention-logit prep
__device__ __forceinline__ void out_phase(
    float* __restrict__ out, int step,
    const float* __restrict__ out_W, const float* __restrict__ out_b,
    const float* __restrict__ attn_W, const float* __restrict__ attn_b,
    const float* __restrict__ dec_emb, const float* __restrict__ h, Smem* sm)
{
    int tid = threadIdx.x, lane = tid & 31, wib = tid >> 5;

    if (wib == 0) {
        // per-lane top-4 over its CTAs
        unsigned long long c0 = 0, c1 = 0, c2 = 0, c3 = 0;
        for (int cc = lane; cc < GRID; cc += 32) {
#pragma unroll
            for (int k = 0; k < 4; k++)
                top4_ins(c0, c1, c2, c3, g_ptop[cc][k]);
        }
        // pop-merge across lanes -> global top-4
        int pos = 0;
        unsigned long long t[4];
#pragma unroll
        for (int k = 0; k < 4; k++) {
            unsigned long long head = (pos == 0) ? c0 : (pos == 1) ? c1 :
                                      (pos == 2) ? c2 : (pos == 3) ? c3 : 0ull;
            unsigned long long mm = wredmaxu64(head);
            t[k] = mm;
            if (head == mm && pos < 4) pos++;
        }
        float M = unpack_max(t[0]);
        float S = 0.f;
        for (int cc = lane; cc < GRID; cc += 32)
            S += g_psum[cc] * expf(unpack_max(g_ptop[cc][0]) - M);
        S = wredsum(S);
        if (lane == 0) {
#pragma unroll
            for (int k = 0; k < 4; k++) sm->top4[k] = t[k];
            sm->bf[0] = M + logf(S);
        }
    }
    __syncthreads();
    float lse = sm->bf[0];

    // write logp row (bf16-based logits, fp32 lse)
    int g = (int)blockIdx.x * BLOCK + tid;
    if (g < VOUT) out[(size_t)step * VOUT + g] = g_logits[g] - lse;

    // fp32 recheck of the 4 candidates (warps 0..3, one row each)
    if (wib < 4) {
        int rk = unpack_idx(sm->top4[wib]);
        const float4* W = (const float4*)(out_W + (size_t)rk * H);
        const float4* h4 = (const float4*)h;
        float a = 0.f;
#pragma unroll 4
        for (int k = lane; k < H4; k += 32) a += dot4(W[k], h4[k]);
        a = wredsum(a);
        if (lane == 0) sm->cand[wib] = packf(a + out_b[rk], rk);
    }
    __syncthreads();
    unsigned long long w = sm->cand[0];
#pragma unroll
    for (int k = 1; k < 4; k++) if (sm->cand[k] > w) w = sm->cand[k];
    int tok = unpack_idx(w);

    // next-step attention logits: two-warp split per CTA row
    if ((int)blockIdx.x < ATT) {
        int r = (int)blockIdx.x;
        if (wib == 0) {        // emb half
            const float4* W  = (const float4*)(attn_W + (size_t)r * 2 * H);
            const float4* e4 = (const float4*)(dec_emb + (size_t)tok * H);
            float a = 0.f;
#pragma unroll 4
            for (int k = lane; k < H4; k += 32) a += dot4(W[k], e4[k]);
            a = wredsum(a);
            if (lane == 0) sm->bf[1] = a;
        } else if (wib == 8) { // h half
            const float4* W  = (const float4*)(attn_W + (size_t)r * 2 * H + H);
            const float4* h4 = (const float4*)h;
            float a = 0.f;
#pragma unroll 4
            for (int k = lane; k < H4; k += 32) a += dot4(W[k], h4[k]);
            a = wredsum(a);
            if (lane == 0) sm->bf[2] = a;
        }
        __syncthreads();
        if (tid == 0) g_attn[r] = sm->bf[1] + sm->bf[2] + attn_b[r];
    }
    if (blockIdx.x == 0 && tid == 0) g_tok = tok;
}

// ---------------- the single persistent kernel ----------------
__global__ void __launch_bounds__(BLOCK, 1) k_all(
    const int* __restrict__ tokens,
    const float* __restrict__ enc_emb,
    const float* __restrict__ enc_Wih, const float* __restrict__ enc_Whh,
    const float* __restrict__ enc_bih, const float* __restrict__ enc_bhh,
    const float* __restrict__ dec_emb,
    const float* __restrict__ attn_W, const float* __restrict__ attn_b,
    const float* __restrict__ comb_W, const float* __restrict__ comb_b,
    const float* __restrict__ dec_Wih, const float* __restrict__ dec_Whh,
    const float* __restrict__ dec_bih, const float* __restrict__ dec_bhh,
    const float* __restrict__ out_W, const float* __restrict__ out_b,
    float* __restrict__ out)
{
    __shared__ Smem sm;
    int tid = threadIdx.x;

    // one-time: convert out_W to bf16 (grid-stride, vectorized)
    {
        const float4* w4 = (const float4*)out_W;
        uint2* dst = (uint2*)g_wbf;
        const int n4 = VOUT * (H / 4);
        for (int i = (int)blockIdx.x * BLOCK + tid; i < n4; i += GRID * BLOCK) {
            float4 v = __ldcs(&w4[i]);
            __nv_bfloat162 lo = __floats2bfloat162_rn(v.x, v.y);
            __nv_bfloat162 hi = __floats2bfloat162_rn(v.z, v.w);
            uint2 o;
            o.x = *(unsigned*)&lo;
            o.y = *(unsigned*)&hi;
            dst[i] = o;
        }
    }

    // init: h0 = 0, padding row of enc_out = 0
    {
        int g = (int)blockIdx.x * BLOCK + tid;
        if (g < H) { g_h[0][g] = 0.f; g_enc_out[ML * H + g] = 0.f; }
    }
    gsync();

    // ---- encoder ----
    for (int t = 0; t < ML; t++) {
        const float* x = enc_emb + (size_t)tokens[t] * H;
        gru_phase(enc_Wih, enc_Whh, enc_bih, enc_bhh, x,
                  g_h[t & 1], g_h[(t & 1) ^ 1], g_enc_out + (size_t)t * H);
        gsync();
    }
    // final encoder hidden in g_h[0]

    // ---- decoder prep (tok = SOS = 0): attention logits (two-warp split) ----
    if ((int)blockIdx.x < ATT) {
        int r = (int)blockIdx.x;
        int wib = tid >> 5, lane = tid & 31;
        if (wib == 0) {
            const float4* W  = (const float4*)(attn_W + (size_t)r * 2 * H);
            const float4* e4 = (const float4*)dec_emb;  // row 0 (SOS)
            float a = 0.f;
#pragma unroll 4
            for (int k = lane; k < H4; k += 32) a += dot4(W[k], e4[k]);
            a = wredsum(a);
            if (lane == 0) sm.bf[1] = a;
        } else if (wib == 8) {
            const float4* W  = (const float4*)(attn_W + (size_t)r * 2 * H + H);
            const float4* h4 = (const float4*)g_h[0];
            float a = 0.f;
#pragma unroll 4
            for (int k = lane; k < H4; k += 32) a += dot4(W[k], h4[k]);
            a = wredsum(a);
            if (lane == 0) sm.bf[2] = a;
        }
        __syncthreads();
        if (tid == 0) g_attn[r] = sm.bf[1] + sm.bf[2] + attn_b[r];
    }
    if (blockIdx.x == 0 && tid == 0) g_tok = 0;
    gsync();

    // ---- decoder ----
    for (int s = 0; s < ML; s++) {
        const float* hc = g_h[s & 1];
        float* hn = g_h[(s & 1) ^ 1];

        ctx_phase(&sm);                                        gsync();
        comb_phase(comb_W, comb_b, dec_emb);                   gsync();
        gru_phase(dec_Wih, dec_Whh, dec_bih, dec_bhh,
                  g_comb, hc, hn, nullptr);                    gsync();
        logits_phase(out_b, hn, &sm);                          gsync();
        out_phase(out, s, out_W, out_b, attn_W, attn_b,
                  dec_emb, hn, &sm);                           gsync();
    }
}

// ---------------- host launcher ----------------
extern "C" void kernel_launch(void* const* d_in, const int* in_sizes, int n_in,
                              void* d_out, int out_size)
{
    const int*   tokens  = (const int*)  d_in[0];
    // d_in[1] = max_length (compile-time ML=128)
    const float* enc_emb = (const float*)d_in[2];
    const float* enc_Wih = (const float*)d_in[3];
    const float* enc_Whh = (const float*)d_in[4];
    const float* enc_bih = (const float*)d_in[5];
    const float* enc_bhh = (const float*)d_in[6];
    const float* dec_emb = (const float*)d_in[7];
    const float* attn_W  = (const float*)d_in[8];
    const float* attn_b  = (const float*)d_in[9];
    const float* comb_W  = (const float*)d_in[10];
    const float* comb_b  = (const float*)d_in[11];
    const float* dec_Wih = (const float*)d_in[12];
    const float* dec_Whh = (const float*)d_in[13];
    const float* dec_bih = (const float*)d_in[14];
    const float* dec_bhh = (const float*)d_in[15];
    const float* out_W   = (const float*)d_in[16];
    const float* out_b   = (const float*)d_in[17];
    float* out = (float*)d_out;

    k_all<<<GRID, BLOCK>>>(tokens, enc_emb, enc_Wih, enc_Whh, enc_bih, enc_bhh,
                           dec_emb, attn_W, attn_b, comb_W, comb_b,
                           dec_Wih, dec_Whh, dec_bih, dec_bhh,
                           out_W, out_b, out);
}